// round 17
// baseline (speedup 1.0000x reference)
#include <cuda_runtime.h>
#include <cuda_bf16.h>
#include <cuda_fp16.h>
#include <stdint.h>
#include <math.h>

#define TT 2048
#define HDIM 2048
#define NHEADS 32
#define NKVH 8
#define HEADD 64
#define SWIN 128
#define QKVD 3072   // HEADD * (NHEADS + 2*NKVH)
#define ROPE_END 2560   // q (2048) + k (512) columns get rope; v beyond

// ---------------- scratch (device globals; no allocation allowed) ----------------
__device__ __half g_qkvh[(size_t)TT * QKVD];   // qkv, fp16, rope already applied
__device__ __half g_nh[TT * HDIM];             // rmsnorm out, fp16
__device__ __half g_ah[TT * HDIM];             // attention out, fp16
__device__ __half g_wqh[(size_t)HDIM * QKVD];  // qkv weight fp16, transposed [N][K]
__device__ __half g_woh[(size_t)HDIM * HDIM];  // out weight fp16, transposed [N][K]

// ---------------- weight transpose to fp16: W[K][N] -> Wh[N][K] ---------
__global__ void splitwh_t(const float* __restrict__ W,
                          __half* __restrict__ Wh, int K, int N) {
    __shared__ float tile[32][33];
    const int kb = blockIdx.y * 32, nb = blockIdx.x * 32;
    const int tx = threadIdx.x, ty = threadIdx.y;   // 32 x 8
    #pragma unroll
    for (int i = 0; i < 32; i += 8)
        tile[ty + i][tx] = W[(size_t)(kb + ty + i) * N + nb + tx];
    __syncthreads();
    #pragma unroll
    for (int i = 0; i < 32; i += 8) {
        int n = nb + ty + i, k = kb + tx;
        Wh[(size_t)n * K + k] = __float2half(tile[tx][ty + i]);
    }
}

// ---------------- RMSNorm (writes fp16) ----------------
__global__ void rmsnorm_kernel(const float* __restrict__ x,
                               const float* __restrict__ scale) {
    int t = blockIdx.x;
    const float* row = x + (size_t)t * HDIM;
    float ss = 0.f;
    for (int i = threadIdx.x; i < HDIM; i += blockDim.x) {
        float v = row[i];
        ss += v * v;
    }
    __shared__ float sh[9];
    #pragma unroll
    for (int o = 16; o; o >>= 1) ss += __shfl_xor_sync(0xffffffffu, ss, o);
    int lane = threadIdx.x & 31, wid = threadIdx.x >> 5;
    if (lane == 0) sh[wid] = ss;
    __syncthreads();
    if (threadIdx.x == 0) {
        float s = 0.f;
        for (int i = 0; i < (int)(blockDim.x >> 5); i++) s += sh[i];
        sh[8] = rsqrtf(s / (float)HDIM + 1e-5f);
    }
    __syncthreads();
    float inv = sh[8];
    for (int i = threadIdx.x; i < HDIM; i += blockDim.x)
        g_nh[(size_t)t * HDIM + i] = __float2half(row[i] * inv * scale[i]);
}

// ---------------- GEMM pieces -------------------------------------------
#define MMAF(d, a, b0, b1) asm volatile( \
  "mma.sync.aligned.m16n8k16.row.col.f32.f16.f16.f32 " \
  "{%0,%1,%2,%3},{%4,%5,%6,%7},{%8,%9},{%0,%1,%2,%3};\n" \
  : "+f"((d)[0]), "+f"((d)[1]), "+f"((d)[2]), "+f"((d)[3]) \
  : "r"((a)[0]), "r"((a)[1]), "r"((a)[2]), "r"((a)[3]), \
    "r"(b0), "r"(b1))

#define LDSM4(r, addr) asm volatile( \
  "ldmatrix.sync.aligned.m8n8.x4.shared.b16 {%0,%1,%2,%3}, [%4];" \
  : "=r"((r)[0]), "=r"((r)[1]), "=r"((r)[2]), "=r"((r)[3]) : "r"(addr))

// BK = 64: row = 128 B data + 16 B pad -> conflict-free ldmatrix
#define SROWB 144u
#define SAB   (128u * SROWB)      // 18432 B per array
#define STAGEB2 (2u * SAB)        // A,B -> 36864 B per stage
#define GSMEM_BYTES2 (2 * STAGEB2)   // 73728 -> 2 CTAs/SM

extern __shared__ unsigned char dynsm[];

// ============ shared GEMM mainloop (BK=64) ============
#define GEMM_MAINLOOP(A_, B_, K_) \
    float acc[2][4][4]; \
    _Pragma("unroll") \
    for (int i = 0; i < 2; i++) \
        _Pragma("unroll") \
        for (int j = 0; j < 4; j++) \
            _Pragma("unroll") \
            for (int r = 0; r < 4; r++) acc[i][j][r] = 0.f; \
    auto load_stage = [&](int stage, int t) { \
        const int k0 = t << 6; \
        const uint32_t sb = smb + stage * STAGEB2; \
        _Pragma("unroll") \
        for (int i = 0; i < 2; i++) { \
            int f = tid + 512 * i; \
            int r = f >> 3; \
            int cb = (f & 7) * 16; \
            { \
                const __half* src = A_ + (size_t)(m0 + r) * K_ + k0 + (cb >> 1); \
                uint32_t dst = sb + r * SROWB + cb; \
                asm volatile("cp.async.cg.shared.global [%0], [%1], 16;" :: "r"(dst), "l"(src)); \
            } \
            { \
                const __half* src = B_ + (size_t)(n0 + r) * K_ + k0 + (cb >> 1); \
                uint32_t dst = sb + SAB + r * SROWB + cb; \
                asm volatile("cp.async.cg.shared.global [%0], [%1], 16;" :: "r"(dst), "l"(src)); \
            } \
        } \
        asm volatile("cp.async.commit_group;"); \
    }; \
    const uint32_t lmrow = lane & 15; \
    const uint32_t lmkh  = (lane >> 4) * 16; \
    const uint32_t aoff0 = (wm + 0  + lmrow) * SROWB + lmkh; \
    const uint32_t aoff1 = (wm + 16 + lmrow) * SROWB + lmkh; \
    const uint32_t boff0 = (wn + 0  + lmrow) * SROWB + lmkh; \
    const uint32_t boff1 = (wn + 16 + lmrow) * SROWB + lmkh; \
    const int trips = K_ >> 6; \
    load_stage(0, 0); \
    load_stage(1, 1); \
    for (int t = 0; t < trips; t++) { \
        if (t < trips - 1) asm volatile("cp.async.wait_group 1;"); \
        else               asm volatile("cp.async.wait_group 0;"); \
        __syncthreads(); \
        const uint32_t sb = smb + (t & 1) * STAGEB2; \
        _Pragma("unroll") \
        for (int ks = 0; ks < 4; ks++) { \
            const uint32_t ko = ks * 32; \
            uint32_t ah[2][4]; \
            LDSM4(ah[0], sb + aoff0 + ko); \
            LDSM4(ah[1], sb + aoff1 + ko); \
            _Pragma("unroll") \
            for (int np = 0; np < 2; np++) { \
                uint32_t bh[4]; \
                LDSM4(bh, sb + SAB + (np ? boff1 : boff0) + ko); \
                _Pragma("unroll") \
                for (int mt = 0; mt < 2; mt++) { \
                    _Pragma("unroll") \
                    for (int sub = 0; sub < 2; sub++) { \
                        float* d = acc[mt][np * 2 + sub]; \
                        MMAF(d, ah[mt], bh[sub], bh[sub + 2]); \
                    } \
                } \
            } \
        } \
        __syncthreads(); \
        if (t + 2 < trips) load_stage(t & 1, t + 2); \
    }

// ---------------- QKV GEMM with rope epilogue, fp16 output ---------------------
__global__ __launch_bounds__(512, 2) void gemm_qkv_rope(
    const __half* __restrict__ A, const __half* __restrict__ Bh,
    const float* __restrict__ bias,
    const float* __restrict__ cos_t, const float* __restrict__ sin_t,
    int N, int K)
{
    const int tid  = threadIdx.x;
    const int lane = tid & 31;
    const int wid  = tid >> 5;
    const int grp  = lane >> 2;
    const int qid  = lane & 3;
    const int wm   = (wid >> 2) * 32;
    const int wn   = (wid & 3) * 32;
    const int m0 = blockIdx.y * 128;
    const int n0 = blockIdx.x * 128;

    uint32_t smb;
    asm("{ .reg .u64 t; cvta.to.shared.u64 t, %1; cvt.u32.u64 %0, t; }"
        : "=r"(smb) : "l"(dynsm));

    GEMM_MAINLOOP(A, Bh, K)

    // epilogue: acc + bias -> smem stage -> rope pairs -> fp16 global
    __syncthreads();
    float* stage = (float*)dynsm;     // [128][132]
    #pragma unroll
    for (int mt = 0; mt < 2; mt++) {
        int rl = wm + mt * 16 + grp;
        #pragma unroll
        for (int nt = 0; nt < 4; nt++) {
            int c = wn + nt * 8 + qid * 2;
            float2 bb = *(const float2*)&bias[n0 + c];
            stage[rl * 132 + c]           = acc[mt][nt][0] + bb.x;
            stage[rl * 132 + c + 1]       = acc[mt][nt][1] + bb.y;
            stage[(rl + 8) * 132 + c]     = acc[mt][nt][2] + bb.x;
            stage[(rl + 8) * 132 + c + 1] = acc[mt][nt][3] + bb.y;
        }
    }
    __syncthreads();
    const bool do_rope = (n0 < ROPE_END);
    for (int f = tid; f < 128 * 32; f += 512) {
        int r = f >> 5;
        int u = f & 31;
        int hh = u >> 4, rr = (u & 15) * 2;
        int c1 = hh * 64 + rr;
        float a0 = stage[r * 132 + c1],      a1 = stage[r * 132 + c1 + 1];
        float b0 = stage[r * 132 + c1 + 32], b1 = stage[r * 132 + c1 + 33];
        int m = m0 + r;
        float o0, o1, o2, o3;
        if (do_rope) {
            float2 cs = *(const float2*)&cos_t[(size_t)m * 32 + rr];
            float2 sn = *(const float2*)&sin_t[(size_t)m * 32 + rr];
            o0 = a0 * cs.x - b0 * sn.x;
            o1 = a1 * cs.y - b1 * sn.y;
            o2 = b0 * cs.x + a0 * sn.x;
            o3 = b1 * cs.y + a1 * sn.y;
        } else {
            o0 = a0; o1 = a1; o2 = b0; o3 = b1;
        }
        __half* dst = g_qkvh + (size_t)m * QKVD + n0;
        *(__half2*)(dst + c1)      = __floats2half2_rn(o0, o1);
        *(__half2*)(dst + c1 + 32) = __floats2half2_rn(o2, o3);
    }
}

// ---------------- fp16 1-term GEMM (out-proj): A @ Bh + bias + resid -> fp32 ----
__global__ __launch_bounds__(512, 2) void gemm_f16_1(
    const __half* __restrict__ A, const __half* __restrict__ Bh,
    const float* __restrict__ bias, const float* __restrict__ resid,
    float* __restrict__ C, int N, int K)
{
    const int tid  = threadIdx.x;
    const int lane = tid & 31;
    const int wid  = tid >> 5;
    const int grp  = lane >> 2;
    const int qid  = lane & 3;
    const int wm   = (wid >> 2) * 32;
    const int wn   = (wid & 3) * 32;
    const int m0 = blockIdx.y * 128;
    const int n0 = blockIdx.x * 128;

    uint32_t smb;
    asm("{ .reg .u64 t; cvta.to.shared.u64 t, %1; cvt.u32.u64 %0, t; }"
        : "=r"(smb) : "l"(dynsm));

    GEMM_MAINLOOP(A, Bh, K)

    #pragma unroll
    for (int mt = 0; mt < 2; mt++) {
        int r0 = m0 + wm + mt * 16 + grp;
        #pragma unroll
        for (int nt = 0; nt < 4; nt++) {
            int c = n0 + wn + nt * 8 + qid * 2;
            float2 bb = *(const float2*)&bias[c];
            float2 ra = *(const float2*)&resid[(size_t)r0 * N + c];
            float2 rb = *(const float2*)&resid[(size_t)(r0 + 8) * N + c];
            float2 v0 = make_float2(acc[mt][nt][0] + bb.x + ra.x,
                                    acc[mt][nt][1] + bb.y + ra.y);
            float2 v1 = make_float2(acc[mt][nt][2] + bb.x + rb.x,
                                    acc[mt][nt][3] + bb.y + rb.y);
            *(float2*)&C[(size_t)r0 * N + c]       = v0;
            *(float2*)&C[(size_t)(r0 + 8) * N + c] = v1;
        }
    }
}

// ---------------- attention v6: 2 CTAs/SM (K fp32, Q/V/S fp16 in smem) --------
#define KMAX 160
#define KT_STRIDE 164                 // fp32 K^T row stride (floats)
#define V2S 33                        // half2 per V row
#define Q2S 32                        // half2 per Q row
#define SHS 164                       // halves per score row
// byte offsets
#define OFFB_KT 0
#define OFFB_V  (64 * KT_STRIDE * 4)                    // 41984
#define OFFB_Q  (OFFB_V + KMAX * V2S * 4)               // 63104
#define OFFB_S  (OFFB_Q + 4 * 32 * Q2S * 4)             // 79488
#define ATT6_BYTES (OFFB_S + 16 * 4 * SHS * 2)          // 100480

__global__ __launch_bounds__(512, 2) void attn6_kernel(const float* __restrict__ sinks) {
    float*    KsT = (float*)dynsm;
    uint32_t* Vs2 = (uint32_t*)(dynsm + OFFB_V);
    uint32_t* Qs2 = (uint32_t*)(dynsm + OFFB_Q);
    __half*   Sh  = (__half*)(dynsm + OFFB_S);

    const int qt = blockIdx.x;
    const int n  = blockIdx.y;
    const int q0 = qt * 32;
    const int k0 = (q0 - SWIN > 0) ? (q0 - SWIN) : 0;
    const int kcnt = q0 + 32 - k0;
    const int tid = threadIdx.x;
    const int lane = tid & 31, wid = tid >> 5;

    const __half* kbase = g_qkvh + (size_t)k0 * QKVD + NHEADS * HEADD + n * HEADD;
    const __half* vbase = kbase + NKVH * HEADD;

    // stage K -> fp32 transposed; V, Q -> fp16 straight copy
    for (int f = tid; f < kcnt * 16; f += 512) {
        int r = f >> 4, dq = (f & 15) * 4;
        uint2 kw = *(const uint2*)(kbase + (size_t)r * QKVD + dq);
        float2 ka = __half22float2(*(__half2*)&kw.x);
        float2 kb = __half22float2(*(__half2*)&kw.y);
        KsT[(dq + 0) * KT_STRIDE + r] = ka.x;
        KsT[(dq + 1) * KT_STRIDE + r] = ka.y;
        KsT[(dq + 2) * KT_STRIDE + r] = kb.x;
        KsT[(dq + 3) * KT_STRIDE + r] = kb.y;
        uint2 vw = *(const uint2*)(vbase + (size_t)r * QKVD + dq);
        Vs2[r * V2S + (dq >> 1)]     = vw.x;
        Vs2[r * V2S + (dq >> 1) + 1] = vw.y;
    }
    for (int f = tid; f < 4 * 32 * 16; f += 512) {
        int g = f >> 9, r = (f >> 4) & 31, dq = (f & 15) * 4;
        uint2 qw = *(const uint2*)(g_qkvh + (size_t)(q0 + r) * QKVD + (n * 4 + g) * HEADD + dq);
        Qs2[(g * 32 + r) * Q2S + (dq >> 1)]     = qw.x;
        Qs2[(g * 32 + r) * Q2S + (dq >> 1) + 1] = qw.y;
    }
    __syncthreads();

    const int g  = wid & 3;
    const int ww = wid >> 2;
    const int h  = n * 4 + g;
    const float snk = sinks[h];
    __half* S4 = Sh + wid * 4 * SHS;

    #pragma unroll
    for (int qq = 0; qq < 2; qq++) {
        const int qi0 = ww * 8 + qq * 4;
        float lmax[4] = {-INFINITY, -INFINITY, -INFINITY, -INFINITY};

        // ---- score pass (K fp32, Q fp16->fp32 per load) ----
        for (int kb = lane; kb < 40; kb += 32) {
            const int kk = kb * 4;
            float sc[4][4];
            #pragma unroll
            for (int p = 0; p < 4; p++)
                sc[p][0] = sc[p][1] = sc[p][2] = sc[p][3] = 0.f;
            #pragma unroll
            for (int d = 0; d < 64; d += 4) {
                float4 kv0 = *(const float4*)&KsT[(d + 0) * KT_STRIDE + kk];
                float4 kv1 = *(const float4*)&KsT[(d + 1) * KT_STRIDE + kk];
                float4 kv2 = *(const float4*)&KsT[(d + 2) * KT_STRIDE + kk];
                float4 kv3 = *(const float4*)&KsT[(d + 3) * KT_STRIDE + kk];
                #pragma unroll
                for (int p = 0; p < 4; p++) {
                    uint2 qw = *(const uint2*)&Qs2[(g * 32 + qi0 + p) * Q2S + (d >> 1)];
                    float2 qa = __half22float2(*(__half2*)&qw.x);
                    float2 qb = __half22float2(*(__half2*)&qw.y);
                    sc[p][0] += qa.x * kv0.x + qa.y * kv1.x + qb.x * kv2.x + qb.y * kv3.x;
                    sc[p][1] += qa.x * kv0.y + qa.y * kv1.y + qb.x * kv2.y + qb.y * kv3.y;
                    sc[p][2] += qa.x * kv0.z + qa.y * kv1.z + qb.x * kv2.z + qb.y * kv3.z;
                    sc[p][3] += qa.x * kv0.w + qa.y * kv1.w + qb.x * kv2.w + qb.y * kv3.w;
                }
            }
            #pragma unroll
            for (int p = 0; p < 4; p++) {
                const int qg = q0 + qi0 + p;
                const int khi = qg - k0;
                int klo = qg - SWIN - k0; if (klo < 0) klo = 0;
                float v0 = (kk + 0 >= klo && kk + 0 <= khi) ? sc[p][0] * 0.125f : -INFINITY;
                float v1 = (kk + 1 >= klo && kk + 1 <= khi) ? sc[p][1] * 0.125f : -INFINITY;
                float v2 = (kk + 2 >= klo && kk + 2 <= khi) ? sc[p][2] * 0.125f : -INFINITY;
                float v3 = (kk + 3 >= klo && kk + 3 <= khi) ? sc[p][3] * 0.125f : -INFINITY;
                *(__half2*)&S4[p * SHS + kk]     = __floats2half2_rn(v0, v1);
                *(__half2*)&S4[p * SHS + kk + 2] = __floats2half2_rn(v2, v3);
                lmax[p] = fmaxf(lmax[p], fmaxf(fmaxf(v0, v1), fmaxf(v2, v3)));
            }
        }
        float inv[4];
        #pragma unroll
        for (int p = 0; p < 4; p++) {
            float m = lmax[p];
            #pragma unroll
            for (int o = 16; o; o >>= 1)
                m = fmaxf(m, __shfl_xor_sync(0xffffffffu, m, o));
            m = fmaxf(m, snk);
            float lsum = 0.f;
            for (int k = lane; k < KMAX; k += 32) {
                float e = expf(__half2float(S4[p * SHS + k]) - m);
                S4[p * SHS + k] = __float2half(e);
                lsum += e;
            }
            #pragma unroll
            for (int o = 16; o; o >>= 1)
                lsum += __shfl_xor_sync(0xffffffffu, lsum, o);
            inv[p] = 1.f / (lsum + expf(snk - m));
        }
        __syncwarp();

        // ---- V pass: lane owns dim pair (2*lane, 2*lane+1) ----
        float a[4][2];
        #pragma unroll
        for (int p = 0; p < 4; p++) a[p][0] = a[p][1] = 0.f;
        for (int k = 0; k < kcnt; k++) {
            uint32_t vv = Vs2[k * V2S + lane];
            float2 v = __half22float2(*(__half2*)&vv);
            #pragma unroll
            for (int p = 0; p < 4; p++) {
                float pp = __half2float(S4[p * SHS + k]);
                a[p][0] += pp * v.x;
                a[p][1] += pp * v.y;
            }
        }
        #pragma unroll
        for (int p = 0; p < 4; p++) {
            const int qg = q0 + qi0 + p;
            *(__half2*)(g_ah + (size_t)qg * HDIM + h * HEADD + 2 * lane) =
                __floats2half2_rn(a[p][0] * inv[p], a[p][1] * inv[p]);
        }
        __syncwarp();
    }
}

// ---------------- launch ----------------
extern "C" void kernel_launch(void* const* d_in, const int* in_sizes, int n_in,
                              void* d_out, int out_size) {
    const float* x          = (const float*)d_in[0];
    const float* scale      = (const float*)d_in[1];
    const float* sinks      = (const float*)d_in[2];
    const float* qkv_kernel = (const float*)d_in[3];
    const float* qkv_bias   = (const float*)d_in[4];
    const float* out_kernel = (const float*)d_in[5];
    const float* out_bias   = (const float*)d_in[6];
    const float* cos_t      = (const float*)d_in[7];
    const float* sin_t      = (const float*)d_in[8];
    // d_in[9] = mask: unused (sliding window applied structurally)
    float* out = (float*)d_out;

    void *p_nh, *p_ah, *p_wqh, *p_woh;
    cudaGetSymbolAddress(&p_nh, g_nh);
    cudaGetSymbolAddress(&p_ah, g_ah);
    cudaGetSymbolAddress(&p_wqh, g_wqh);
    cudaGetSymbolAddress(&p_woh, g_woh);

    static bool attr_set = false;
    if (!attr_set) {
        cudaFuncSetAttribute(gemm_qkv_rope,
                             cudaFuncAttributeMaxDynamicSharedMemorySize, GSMEM_BYTES2);
        cudaFuncSetAttribute(gemm_f16_1,
                             cudaFuncAttributeMaxDynamicSharedMemorySize, GSMEM_BYTES2);
        cudaFuncSetAttribute(attn6_kernel,
                             cudaFuncAttributeMaxDynamicSharedMemorySize, ATT6_BYTES);
        attr_set = true;
    }

    // transpose weights to fp16 [N][K]
    splitwh_t<<<dim3(QKVD / 32, HDIM / 32), dim3(32, 8)>>>(
        qkv_kernel, (__half*)p_wqh, HDIM, QKVD);
    splitwh_t<<<dim3(HDIM / 32, HDIM / 32), dim3(32, 8)>>>(
        out_kernel, (__half*)p_woh, HDIM, HDIM);

    rmsnorm_kernel<<<TT, 256>>>(x, scale);

    // QKV GEMM + fused rope, fp16 output
    gemm_qkv_rope<<<dim3(QKVD / 128, TT / 128), 512, GSMEM_BYTES2>>>(
        (const __half*)p_nh, (const __half*)p_wqh,
        qkv_bias, cos_t, sin_t, QKVD, HDIM);

    attn6_kernel<<<dim3(TT / 32, NKVH), 512, ATT6_BYTES>>>(sinks);

    // out-proj + residual: fp16 1-term, fp32 out
    gemm_f16_1<<<dim3(HDIM / 128, TT / 128), 512, GSMEM_BYTES2>>>(
        (const __half*)p_ah, (const __half*)p_woh,
        out_bias, x, out, HDIM, HDIM);
}